// round 14
// baseline (speedup 1.0000x reference)
#include <cuda_runtime.h>
#include <math_constants.h>
#include <cstdint>

#define W      8192
#define ROWS   4096      // 16 * 1 * 256
#define NLAG   4096      // W / 2
#define TPB    512
#define G      4         // float4 groups per thread
#define SEG    2048      // floats per group stripe (TPB * 4)
#define NWARP  (TPB / 32)
#define CAP    256       // candidate buffer capacity
#define GRID   304       // 152 SMs * 2 resident blocks (persistent)
#define TILE_BYTES (W * 4)

__device__ __forceinline__ uint32_t smem_u32(const void* p) {
    uint32_t a;
    asm("{ .reg .u64 t; cvta.to.shared.u64 t, %1; cvt.u32.u64 %0, t; }"
        : "=r"(a) : "l"(p));
    return a;
}

__device__ __forceinline__ void mbar_wait(uint32_t mbar, uint32_t par) {
    uint32_t done;
    asm volatile(
        "{\n\t.reg .pred p;\n\t"
        "mbarrier.try_wait.parity.acquire.cta.shared::cta.b64 p, [%1], %2;\n\t"
        "selp.b32 %0, 1, 0, p;\n\t}"
        : "=r"(done) : "r"(mbar), "r"(par) : "memory");
    if (!done) {
        asm volatile(
            "{\n\t.reg .pred P1;\n\t"
            "W_%=:\n\t"
            "mbarrier.try_wait.parity.acquire.cta.shared::cta.b64 P1, [%0], %1, 0x989680;\n\t"
            "@P1 bra.uni D_%=;\n\t"
            "bra.uni W_%=;\n\t"
            "D_%=:\n\t}"
            :: "r"(mbar), "r"(par) : "memory");
    }
}

__device__ __forceinline__ bool better(float v, int i, float v2, int i2) {
    return (v > v2) || (v == v2 && i < i2);
}

__device__ __forceinline__ void ins3(float v, int i,
                                     float& s0, int& i0,
                                     float& s1, int& i1,
                                     float& s2, int& i2) {
    if (better(v, i, s0, i0)) {
        s2 = s1; i2 = i1;
        s1 = s0; i1 = i0;
        s0 = v;  i0 = i;
    } else if (better(v, i, s1, i1)) {
        s2 = s1; i2 = i1;
        s1 = v;  i1 = i;
    } else if (better(v, i, s2, i2)) {
        s2 = v;  i2 = i;
    }
}

// Merge sorted (desc) value triple (b0,b1,b2) into (a0,a1,a2). FMNMX net.
__device__ __forceinline__ void merge3(float& a0, float& a1, float& a2,
                                       float b0, float b1, float b2) {
    float r0 = fmaxf(a0, b0);
    float x  = fminf(a0, b0);
    float y  = fmaxf(a1, b1);
    float z  = fminf(a1, b1);
    float r1 = fmaxf(x, y);
    float s  = fminf(x, y);
    float r2 = fmaxf(fmaxf(s, z), fmaxf(a2, b2));
    a0 = r0; a1 = r1; a2 = r2;
}

__global__ __launch_bounds__(TPB, 2)
void peaks_kernel(const float* __restrict__ x, float* __restrict__ out) {
    extern __shared__ __align__(128) float s_tiles[];   // 2 * W floats (dynamic)
    __shared__ __align__(8) unsigned long long s_mbar[2];
    __shared__ float s_wmax[NWARP];
    __shared__ float s_t;
    __shared__ int   s_cnt;
    __shared__ float s_val[CAP];
    __shared__ int   s_idx[CAP];

    const int t   = threadIdx.x;
    const int lid = t & 31;
    const int wid = t >> 5;
    const unsigned fm = 0xffffffffu;
    const uint32_t mb0 = smem_u32(&s_mbar[0]);
    const uint32_t mb1 = smem_u32(&s_mbar[1]);

    if (t == 0) {
        s_cnt = 0;
        asm volatile("mbarrier.init.shared.b64 [%0], %1;" :: "r"(mb0), "r"(1) : "memory");
        asm volatile("mbarrier.init.shared.b64 [%0], %1;" :: "r"(mb1), "r"(1) : "memory");
        asm volatile("fence.proxy.async.shared::cta;" ::: "memory");
    }
    __syncthreads();

    // ---- Prologue: prefetch first row into buffer 0 ----
    if (t == 0) {
        asm volatile("mbarrier.arrive.expect_tx.shared.b64 _, [%0], %1;"
                     :: "r"(mb0), "r"((uint32_t)TILE_BYTES) : "memory");
        asm volatile(
            "cp.async.bulk.shared::cta.global.mbarrier::complete_tx::bytes "
            "[%0], [%1], %2, [%3];"
            :: "r"(smem_u32(s_tiles)), "l"(x + (size_t)blockIdx.x * W),
               "r"((uint32_t)TILE_BYTES), "r"(mb0) : "memory");
    }

    int k = 0;   // iteration counter: buf = k&1, wait parity = (k>>1)&1
    for (int row = blockIdx.x; row < ROWS; row += GRID, k++) {
        const int      buf  = k & 1;
        const uint32_t mbar = buf ? mb1 : mb0;
        const float*   tile = s_tiles + buf * W;

        // ---- Prefetch next row into the other buffer (readers finished at
        //      previous iteration's B4; fence bridges generic->async proxy) ----
        const int nxt = row + GRID;
        if (t == 0 && nxt < ROWS) {
            const uint32_t mnext = buf ? mb0 : mb1;
            asm volatile("fence.proxy.async.shared::cta;" ::: "memory");
            asm volatile("mbarrier.arrive.expect_tx.shared.b64 _, [%0], %1;"
                         :: "r"(mnext), "r"((uint32_t)TILE_BYTES) : "memory");
            asm volatile(
                "cp.async.bulk.shared::cta.global.mbarrier::complete_tx::bytes "
                "[%0], [%1], %2, [%3];"
                :: "r"(smem_u32(s_tiles + (1 - buf) * W)),
                   "l"(x + (size_t)nxt * W),
                   "r"((uint32_t)TILE_BYTES), "r"(mnext) : "memory");
        }

        // ---- Wait for current tile (HW sleep) ----
        mbar_wait(mbar, (uint32_t)((k >> 1) & 1));

        // ---- Phase 1: raw thread max from smem (LDS.128, conflict-free) ----
        float myMax = -CUDART_INF_F;
        float fb = -CUDART_INF_F, lb = -CUDART_INF_F;
#pragma unroll
        for (int g = 0; g < G; g++) {
            const float4 v = *reinterpret_cast<const float4*>(tile + g * SEG + t * 4);
            myMax = fmaxf(myMax, fmaxf(fmaxf(v.x, v.y), fmaxf(v.z, v.w)));
            fb = fmaxf(fb, v.x);   // only lane 0's value consumed
            lb = fmaxf(lb, v.w);   // only lane 31's value consumed
        }

        float wm = myMax;
#pragma unroll
        for (int off = 16; off; off >>= 1)
            wm = fmaxf(wm, __shfl_down_sync(fm, wm, off));
        wm = __shfl_sync(fm, wm, 0);

        const float bmax = fmaxf(__shfl_sync(fm, fb, 0), __shfl_sync(fm, lb, 31));
        if (lid == 0) {
            float safe;
            if (wm > bmax) {
                safe = wm;   // strictly interior => exact achievable peak score
            } else {
                // rare fallback: exact edge-peak scores of the 8 boundary elems
                float ep = 0.0f;
#pragma unroll
                for (int g = 0; g < G; g++) {
                    const int pb = g * SEG + wid * 128;
                    const float v0 = tile[pb];
                    const float l0 = (pb > 0) ? tile[pb - 1] : -CUDART_INF_F;
                    if (v0 >= fmaxf(l0, tile[pb + 1])) ep = fmaxf(ep, v0);
                    const int pr = pb + 127;
                    const float v1 = tile[pr];
                    const float r1 = (pr + 1 < W) ? tile[pr + 1] : -CUDART_INF_F;
                    if (v1 >= fmaxf(tile[pr - 1], r1)) ep = fmaxf(ep, v1);
                }
                safe = ep;
            }
            s_wmax[wid] = safe;
        }
        __syncthreads();                                      // B2

        if (wid == 0) {
            float u0 = (lid < NWARP) ? s_wmax[lid] : -CUDART_INF_F;
            float u1 = -CUDART_INF_F, u2 = -CUDART_INF_F;
#pragma unroll
            for (int off = 8; off; off >>= 1) {
                float b0 = __shfl_down_sync(fm, u0, off);
                float b1 = __shfl_down_sync(fm, u1, off);
                float b2 = __shfl_down_sync(fm, u2, off);
                merge3(u0, u1, u2, b0, b1, b2);
            }
            if (lid == 0) s_t = u2;
        }
        __syncthreads();                                      // B3

        // ---- Phase 2: gated threads recompute exact scores from smem ----
        const float thr = s_t;
        if (myMax >= thr) {
#pragma unroll
            for (int g = 0; g < G; g++) {
                const int gi = g * SEG + t * 4;
#pragma unroll
                for (int j = 0; j < 4; j++) {
                    const int p = gi + j;
                    const float v = tile[p];
                    const float l = (p > 0)     ? tile[p - 1] : -CUDART_INF_F;
                    const float r = (p + 1 < W) ? tile[p + 1] : -CUDART_INF_F;
                    const float sc = (v >= fmaxf(l, r)) ? v : 0.0f;
                    if (sc >= thr && sc > 0.0f) {
                        int pos = atomicAdd(&s_cnt, 1);
                        if (pos < CAP) { s_val[pos] = sc; s_idx[pos] = p; }
                    }
                }
            }
        }
        __syncthreads();                                      // B4

        // ---- Thread 0: exact top-3 + outputs; reset s_cnt for next row ----
        if (t == 0) {
            int n = s_cnt; if (n > CAP) n = CAP;
            s_cnt = 0;   // safe: next atomics happen only after next B3,
                         // which requires thread 0 (post-reset) to arrive.
            float s0 = -CUDART_INF_F, s1 = -CUDART_INF_F, s2 = -CUDART_INF_F;
            int   i0 = 0x7fffffff,    i1 = 0x7fffffff,    i2 = 0x7fffffff;
            for (int q = 0; q < n; q++)
                ins3(s_val[q], s_idx[q], s0, i0, s1, i1, s2, i2);

            // Output layout (return order, all fp32):
            //   [0       , ROWS*3) : neighbor_score
            //   [ROWS*3  , ROWS*6) : topk_scores
            //   [ROWS*6  , ROWS*9) : topk_index (int values, exact in fp32)
            const int top = i0;
#pragma unroll
            for (int q = 0; q < 3; q++) {
                int nb = top - 1 + q;
                nb = nb < 0 ? 0 : (nb > W - 1 ? W - 1 : nb);
                out[(size_t)row * 3 + q] = tile[nb];
            }
            const float ts[3] = {s0, s1, s2};
            const int   ti[3] = {i0, i1, i2};
#pragma unroll
            for (int q = 0; q < 3; q++) {
                out[(size_t)ROWS * 3 + (size_t)row * 3 + q] = ts[q];
                out[(size_t)ROWS * 6 + (size_t)row * 3 + q] = (float)(ti[q] - NLAG);
            }
        }
        // No end-of-iteration barrier needed: next-iteration shared writes
        // (s_wmax at B2, atomics after B3) are barrier-ordered against this
        // iteration's readers, and the prefetch target buffer's readers all
        // arrived at this iteration's B4.
    }
}

extern "C" void kernel_launch(void* const* d_in, const int* in_sizes, int n_in,
                              void* d_out, int out_size) {
    const float* x = (const float*)d_in[0];
    float* out = (float*)d_out;
    (void)in_sizes; (void)n_in; (void)out_size;
    cudaFuncSetAttribute(peaks_kernel,
                         cudaFuncAttributeMaxDynamicSharedMemorySize,
                         2 * TILE_BYTES);
    peaks_kernel<<<GRID, TPB, 2 * TILE_BYTES>>>(x, out);
}

// round 15
// speedup vs baseline: 1.0696x; 1.0696x over previous
#include <cuda_runtime.h>
#include <math_constants.h>
#include <cstdint>

#define W      8192
#define ROWS   4096      // 16 * 1 * 256
#define NLAG   4096      // W / 2
#define TPB    256
#define G      8         // float4 groups per thread (from smem)
#define SEG    1024      // floats per group stripe (TPB * 4)
#define NWARP  (TPB / 32)
#define CAP    256       // candidate buffer capacity
#define TILE_BYTES (W * 4)

__device__ __forceinline__ uint32_t smem_u32(const void* p) {
    uint32_t a;
    asm("{ .reg .u64 t; cvta.to.shared.u64 t, %1; cvt.u32.u64 %0, t; }"
        : "=r"(a) : "l"(p));
    return a;
}

__device__ __forceinline__ bool better(float v, int i, float v2, int i2) {
    return (v > v2) || (v == v2 && i < i2);
}

__device__ __forceinline__ void ins3(float v, int i,
                                     float& s0, int& i0,
                                     float& s1, int& i1,
                                     float& s2, int& i2) {
    if (better(v, i, s0, i0)) {
        s2 = s1; i2 = i1;
        s1 = s0; i1 = i0;
        s0 = v;  i0 = i;
    } else if (better(v, i, s1, i1)) {
        s2 = s1; i2 = i1;
        s1 = v;  i1 = i;
    } else if (better(v, i, s2, i2)) {
        s2 = v;  i2 = i;
    }
}

// Merge sorted (desc) value triple (b0,b1,b2) into (a0,a1,a2). FMNMX net.
__device__ __forceinline__ void merge3(float& a0, float& a1, float& a2,
                                       float b0, float b1, float b2) {
    float r0 = fmaxf(a0, b0);
    float x  = fminf(a0, b0);
    float y  = fmaxf(a1, b1);
    float z  = fminf(a1, b1);
    float r1 = fmaxf(x, y);
    float s  = fminf(x, y);
    float r2 = fmaxf(fmaxf(s, z), fmaxf(a2, b2));
    a0 = r0; a1 = r1; a2 = r2;
}

__global__ __launch_bounds__(TPB, 6)
void peaks_kernel(const float* __restrict__ x, float* __restrict__ out) {
    extern __shared__ __align__(128) float s_tile[];   // W floats (dynamic)
    __shared__ __align__(8)  unsigned long long s_mbar;
    __shared__ float s_wmax[NWARP];
    __shared__ float s_t;
    __shared__ int   s_cnt;
    __shared__ float s_val[CAP];
    __shared__ int   s_idx[CAP];

    const int row = blockIdx.x;
    const float* __restrict__ xr = x + (size_t)row * W;
    const int t   = threadIdx.x;
    const int lid = t & 31;
    const int wid = t >> 5;
    const unsigned fm = 0xffffffffu;
    const uint32_t mbar = smem_u32(&s_mbar);

    // ---- TMA bulk stage: gmem row -> smem tile ----
    if (t == 0) {
        s_cnt = 0;
        asm volatile("mbarrier.init.shared.b64 [%0], %1;"
                     :: "r"(mbar), "r"(1) : "memory");
        asm volatile("fence.proxy.async.shared::cta;" ::: "memory");
    }
    __syncthreads();                                          // B0
    if (t == 0) {
        asm volatile("mbarrier.arrive.expect_tx.shared.b64 _, [%0], %1;"
                     :: "r"(mbar), "r"((uint32_t)TILE_BYTES) : "memory");
        asm volatile(
            "cp.async.bulk.shared::cta.global.mbarrier::complete_tx::bytes "
            "[%0], [%1], %2, [%3];"
            :: "r"(smem_u32(s_tile)), "l"(xr),
               "r"((uint32_t)TILE_BYTES), "r"(mbar) : "memory");
    }
    // All threads wait (HW sleep) for the tile.
    {
        uint32_t done;
        asm volatile(
            "{\n\t.reg .pred p;\n\t"
            "mbarrier.try_wait.parity.acquire.cta.shared::cta.b64 p, [%1], %2;\n\t"
            "selp.b32 %0, 1, 0, p;\n\t}"
            : "=r"(done) : "r"(mbar), "r"(0u) : "memory");
        if (!done) {
            asm volatile(
                "{\n\t.reg .pred P1;\n\t"
                "W_%=:\n\t"
                "mbarrier.try_wait.parity.acquire.cta.shared::cta.b64 P1, [%0], %1, 0x989680;\n\t"
                "@P1 bra.uni D_%=;\n\t"
                "bra.uni W_%=;\n\t"
                "D_%=:\n\t}"
                :: "r"(mbar), "r"(0u) : "memory");
        }
    }

    // ---- Phase 1: raw thread max from smem (LDS.128, conflict-free) ----
    float myMax = -CUDART_INF_F;
    float fb = -CUDART_INF_F, lb = -CUDART_INF_F;   // segment boundary accums
#pragma unroll
    for (int g = 0; g < G; g++) {
        const float4 v = *reinterpret_cast<const float4*>(s_tile + g * SEG + t * 4);
        myMax = fmaxf(myMax, fmaxf(fmaxf(v.x, v.y), fmaxf(v.z, v.w)));
        fb = fmaxf(fb, v.x);    // only lane 0's value consumed
        lb = fmaxf(lb, v.w);    // only lane 31's value consumed
    }

    // ---- Single warp reduce of raw max + broadcast ----
    float wm = myMax;
#pragma unroll
    for (int off = 16; off; off >>= 1)
        wm = fmaxf(wm, __shfl_down_sync(fm, wm, off));
    wm = __shfl_sync(fm, wm, 0);

    // ---- Warp-safe value (computed on lane 0 only) ----
    const float bmax = fmaxf(__shfl_sync(fm, fb, 0), __shfl_sync(fm, lb, 31));
    if (lid == 0) {
        float safe;
        if (wm > bmax) {
            // warp raw max strictly interior to its 128-float segment:
            // it IS a peak => exact achievable score.
            safe = wm;
        } else {
            // rare fallback: exact edge-peak scores of the 16 boundary elems
            // (achievable scores -> thr stays achievable -> no flood).
            float ep = 0.0f;
#pragma unroll
            for (int g = 0; g < G; g++) {
                const int pb = g * SEG + wid * 128;      // segment base
                const float v0 = s_tile[pb];
                const float l0 = (pb > 0) ? s_tile[pb - 1] : -CUDART_INF_F;
                if (v0 >= fmaxf(l0, s_tile[pb + 1])) ep = fmaxf(ep, v0);
                const int pr = pb + 127;
                const float v1 = s_tile[pr];
                const float r1 = (pr + 1 < W) ? s_tile[pr + 1] : -CUDART_INF_F;
                if (v1 >= fmaxf(s_tile[pr - 1], r1)) ep = fmaxf(ep, v1);
            }
            safe = ep;
        }
        s_wmax[wid] = safe;
    }
    __syncthreads();                                          // B2

    // ---- Warp 0 ONLY: 3rd-largest of 8 warp values -> block threshold ----
    if (wid == 0) {
        float u0 = (lid < NWARP) ? s_wmax[lid] : -CUDART_INF_F;
        float u1 = -CUDART_INF_F, u2 = -CUDART_INF_F;
#pragma unroll
        for (int off = 4; off; off >>= 1) {
            float b0 = __shfl_down_sync(fm, u0, off);
            float b1 = __shfl_down_sync(fm, u1, off);
            float b2 = __shfl_down_sync(fm, u2, off);
            merge3(u0, u1, u2, b0, b1, b2);
        }
        if (lid == 0) s_t = u2;
    }
    __syncthreads();                                          // B3

    // ---- Phase 2: gated threads recompute exact scores from smem ----
    const float thr = s_t;
    if (myMax >= thr) {   // raw max >= any peak score in chunk: safe gate
#pragma unroll
        for (int g = 0; g < G; g++) {
            const int gi = g * SEG + t * 4;
#pragma unroll
            for (int j = 0; j < 4; j++) {
                const int p = gi + j;
                const float v = s_tile[p];
                const float l = (p > 0)     ? s_tile[p - 1] : -CUDART_INF_F;
                const float r = (p + 1 < W) ? s_tile[p + 1] : -CUDART_INF_F;
                const float sc = (v >= fmaxf(l, r)) ? v : 0.0f;
                if (sc >= thr && sc > 0.0f) {
                    int pos = atomicAdd(&s_cnt, 1);
                    if (pos < CAP) { s_val[pos] = sc; s_idx[pos] = p; }
                }
            }
        }
    }
    __syncthreads();                                          // B4

    // ---- Thread 0: exact top-3 over tiny candidate list, then outputs ----
    if (t == 0) {
        int n = s_cnt; if (n > CAP) n = CAP;
        float s0 = -CUDART_INF_F, s1 = -CUDART_INF_F, s2 = -CUDART_INF_F;
        int   i0 = 0x7fffffff,    i1 = 0x7fffffff,    i2 = 0x7fffffff;
        for (int k = 0; k < n; k++)
            ins3(s_val[k], s_idx[k], s0, i0, s1, i1, s2, i2);

        // Output layout (return order, all fp32):
        //   [0       , ROWS*3) : neighbor_score
        //   [ROWS*3  , ROWS*6) : topk_scores
        //   [ROWS*6  , ROWS*9) : topk_index (int values, exact in fp32)
        const int top = i0;
#pragma unroll
        for (int k = 0; k < 3; k++) {
            int nb = top - 1 + k;
            nb = nb < 0 ? 0 : (nb > W - 1 ? W - 1 : nb);
            out[(size_t)row * 3 + k] = s_tile[nb];
        }
        const float ts[3] = {s0, s1, s2};
        const int   ti[3] = {i0, i1, i2};
#pragma unroll
        for (int k = 0; k < 3; k++) {
            out[(size_t)ROWS * 3 + (size_t)row * 3 + k] = ts[k];
            out[(size_t)ROWS * 6 + (size_t)row * 3 + k] = (float)(ti[k] - NLAG);
        }
    }
}

extern "C" void kernel_launch(void* const* d_in, const int* in_sizes, int n_in,
                              void* d_out, int out_size) {
    const float* x = (const float*)d_in[0];
    float* out = (float*)d_out;
    (void)in_sizes; (void)n_in; (void)out_size;
    cudaFuncSetAttribute(peaks_kernel,
                         cudaFuncAttributeMaxDynamicSharedMemorySize,
                         TILE_BYTES);
    peaks_kernel<<<ROWS, TPB, TILE_BYTES>>>(x, out);
}